// round 14
// baseline (speedup 1.0000x reference)
#include <cuda_runtime.h>
#include <cuda_fp16.h>
#include <math.h>

#define NB    256
#define TP    32
#define TFUT  256
#define HH    100
#define NF    275
#define HGG   75
#define HOO   75
#define NTHR  576
#define HALF  288
#define NCTA  128

// ---- weights in global scratch (layouts identical to R13) ----
__device__ __align__(16) float g_W1P[28600];          // W1 fp32 k-paired
__device__ __align__(16) unsigned int g_W3H[14000];   // W3 fp16 k-paired
__device__ __align__(16) __half2 g_W2H[276 * 138];    // W2 fp16 n-paired, k-major
__device__ __align__(16) float g_WhhT[100 * 300];
__device__ __align__(16) float g_oW1T[100 * 75];
__device__ __align__(16) float g_oW2T[75 * 75];
__device__ float g_hB[NB * HH];
__device__ float g_gx[NB * 2];
__device__ float g_z0[NB * HH];

// ---- shared layout (float offsets): shared weights + 2 per-half blocks ----
#define OFF_W1P  0        // 28600 floats
#define OFF_W3H  28600    // 14000 uints
#define OFF_HALF 42600
#define HB_STRIDE 2048
#define HB_IN   0         // float[104]  (101..103 zero)
#define HB_HID  104       // float[280]  (275..279 zero)
#define HB_A2   384       // float[280]  (275..279 zero)
#define HB_Y    664       // float[100]
#define HB_KS   764       // float[100]
#define HB_L2P  864       // float2[138]
#define HB_L3P  1140      // float[100]
#define SMEM_BYTES ((OFF_HALF + 2 * HB_STRIDE) * 4)   // 186,784 B

__device__ __forceinline__ void hbar(int id) {
    asm volatile("bar.sync %0, %1;" :: "r"(id), "r"(HALF) : "memory");
}
__device__ __forceinline__ float leaky1(float x) {
    const float SL = 1.0f / 5.5f;
    return x >= 0.f ? x : x * SL;
}
__device__ __forceinline__ float sigm1(float x) { return 1.f / (1.f + expf(-x)); }

// ---- W2 consume/refill (scalar x broadcast, 2 outputs per thread) ----
#define W2R16(R, ROW0) {                                                      \
    _Pragma("unroll")                                                         \
    for (int i_ = 0; i_ < 16; i_++)                                           \
        R[i_] = __ldcg((const unsigned int*)(ph + ((ROW0) + i_) * 138)); }

#define W2C16(R, OFF) {                                                       \
    _Pragma("unroll")                                                         \
    for (int i_ = 0; i_ < 16; i_++) {                                         \
        float2 wf_ = __half22float2(*(const __half2*)&R[i_]);                 \
        float xv_ = xs[(OFF) + i_];                                           \
        if (i_ & 1) { c01 = fmaf(wf_.x, xv_, c01); c11 = fmaf(wf_.y, xv_, c11); } \
        else        { c00 = fmaf(wf_.x, xv_, c00); c10 = fmaf(wf_.y, xv_, c10); } \
    } }

// ---- One RK4 stage for ONE batch row on ONE half (288 threads) ----
__device__ __forceinline__ void field_stage(int ht, int bid, float* sm, float* hb,
        int stage, float dt, float tnext, bool write_in,
        float rb1, float rb2a, float rb2b, float rb3) {
    float* s_in = hb + HB_IN;
    float* s_hid = hb + HB_HID;
    float* s_a2 = hb + HB_A2;
    float* s_y = hb + HB_Y;
    float* s_ks = hb + HB_KS;
    float2* s_l2p = (float2*)(hb + HB_L2P);
    float* s_l3p = hb + HB_L3P;

    int q = ht / 138, j = ht - q * 138;
    bool actL2 = (q < 2);
    const __half2* ph = g_W2H + (q * 138) * 138 + j;

    // W2 prefetch (rows 0..31 of slice + tail) before L1 compute
    unsigned int A[16], B[16], T[10];
    if (actL2) {
        W2R16(A, 0)
        W2R16(B, 16)
#pragma unroll
        for (int i = 0; i < 10; i++)
            T[i] = __ldcg((const unsigned int*)(ph + (128 + i) * 138));
    }

    // ---- L1: 101 -> 275, full dot per thread ----
    if (ht < NF) {
        const float2* wp = ((const float2*)(sm + OFF_W1P)) + ht;
        const float2* x2 = (const float2*)s_in;
        float a0 = 0.f, a1 = 0.f, b0 = 0.f, b1 = 0.f;
#pragma unroll
        for (int kp = 0; kp < 52; kp += 2) {
            float2 w0 = wp[kp * 275], w1 = wp[(kp + 1) * 275];
            float2 xA = x2[kp], xB = x2[kp + 1];
            a0 = fmaf(w0.x, xA.x, a0); a1 = fmaf(w0.y, xA.y, a1);
            b0 = fmaf(w1.x, xB.x, b0); b1 = fmaf(w1.y, xB.y, b1);
        }
        s_hid[ht] = tanhf((a0 + a1) + (b0 + b1) + rb1);
    }
    hbar(bid);

    // ---- L2: 275 -> 275, fp16 W2 stream, 2-way k-split, 2 outputs/thread ----
    float accA = 0.f, accB = 0.f;
    if (actL2) {
        const float* xs = s_hid + q * 138;
        float c00 = 0.f, c01 = 0.f, c10 = 0.f, c11 = 0.f;
        W2C16(A, 0)   W2R16(A, 32)
        W2C16(B, 16)  W2R16(B, 48)
        W2C16(A, 32)  W2R16(A, 64)
        W2C16(B, 48)  W2R16(B, 80)
        W2C16(A, 64)  W2R16(A, 96)
        W2C16(B, 80)  W2R16(B, 112)
        W2C16(A, 96)
        W2C16(B, 112)
#pragma unroll
        for (int i = 0; i < 10; i++) {
            float2 wf = __half22float2(*(const __half2*)&T[i]);
            float xv = xs[128 + i];
            if (i & 1) { c01 = fmaf(wf.x, xv, c01); c11 = fmaf(wf.y, xv, c11); }
            else       { c00 = fmaf(wf.x, xv, c00); c10 = fmaf(wf.y, xv, c10); }
        }
        accA = c00 + c01; accB = c10 + c11;
        if (q) s_l2p[j] = make_float2(accA, accB);
    }
    hbar(bid);
    if (actL2 && !q) {   // ht < 138
        float2 p = s_l2p[j];
        s_a2[2 * j]     = tanhf(accA + p.x + rb2a);
        s_a2[2 * j + 1] = tanhf(accB + p.y + rb2b);
    }
    hbar(bid);

    // ---- L3: 275 -> 100, fp16 W3 in smem, 2-way k-split ----
    int q3 = ht / 100, n3 = ht - q3 * 100;
    float l3 = 0.f;
    if (ht < 200) {
        const unsigned int* w3 = ((const unsigned int*)(sm + OFF_W3H)) + n3;
        const float2* x2 = (const float2*)s_a2;
        int kp0 = q3 * 70;
        float a0 = 0.f, a1 = 0.f, b0 = 0.f, b1 = 0.f;
#pragma unroll
        for (int u = 0; u < 70; u += 2) {
            unsigned int w0u = w3[(kp0 + u) * 100];
            unsigned int w1u = w3[(kp0 + u + 1) * 100];
            float2 w0 = __half22float2(*(const __half2*)&w0u);
            float2 w1 = __half22float2(*(const __half2*)&w1u);
            float2 xA = x2[kp0 + u], xB = x2[kp0 + u + 1];
            a0 = fmaf(w0.x, xA.x, a0); a1 = fmaf(w0.y, xA.y, a1);
            b0 = fmaf(w1.x, xB.x, b0); b1 = fmaf(w1.y, xB.y, b1);
        }
        l3 = (a0 + a1) + (b0 + b1);
        if (q3) s_l3p[n3] = l3;
    }
    hbar(bid);
    if (ht < 100) {
        float f = tanhf(l3 + s_l3p[ht] + rb3);
        float y = s_y[ht];
        if (stage == 0) {
            s_ks[ht] = f;
            s_in[1 + ht] = fmaf(0.5f * dt, f, y);
        } else if (stage == 1) {
            float k = s_ks[ht];
            s_ks[ht] = k + 2.f * f;
            s_in[1 + ht] = fmaf(0.5f * dt, f, y);
        } else if (stage == 2) {
            float k = s_ks[ht];
            s_ks[ht] = k + 2.f * f;
            s_in[1 + ht] = fmaf(dt, f, y);
        } else {
            float k = s_ks[ht];
            float yn = y + dt * (k + f) / 6.f;
            s_y[ht] = yn;
            if (write_in) s_in[1 + ht] = yn;
        }
        if (ht == 0 && (stage < 3 || write_in)) s_in[0] = tnext;
    }
    hbar(bid);
}

// ---- RK4, NSUB=2, per half ----
__device__ __forceinline__ void integrate2(int ht, int bid, float* sm, float* hb,
        float t0, float t1, float rb1, float rb2a, float rb2b, float rb3) {
    float* s_in = hb + HB_IN;
    float* s_y = hb + HB_Y;
    float dt = (t1 - t0) * 0.5f;
    if (ht < HH) s_in[1 + ht] = s_y[ht];
    if (ht == 0) s_in[0] = t0;
    hbar(bid);
#pragma unroll 1
    for (int st = 0; st < 8; st++) {
        int stage = st & 3, sub = st >> 2;
        float tb = t0 + sub * dt;
        float tnext = (stage <= 1) ? tb + 0.5f * dt : tb + dt;
        field_stage(ht, bid, sm, hb, stage, dt, tnext, (st == 3),
                    rb1, rb2a, rb2b, rb3);
    }
}

// ---- shared init (full CTA) ----
__device__ __forceinline__ void load_shared_weights(int tid, float* sm) {
    const float4* s1 = (const float4*)g_W1P;
    float4* d1 = (float4*)sm;
    for (int i = tid; i < 28600 / 4; i += NTHR) d1[i] = s1[i];
    const uint4* s2 = (const uint4*)g_W3H;
    uint4* d2 = (uint4*)(sm + OFF_W3H);
    for (int i = tid; i < 14000 / 4; i += NTHR) d2[i] = s2[i];
    if (tid < 2) {
        float* hb = sm + OFF_HALF + tid * HB_STRIDE;
        hb[HB_IN + 101] = hb[HB_IN + 102] = hb[HB_IN + 103] = 0.f;
        for (int i = 275; i < 280; i++) { hb[HB_HID + i] = 0.f; hb[HB_A2 + i] = 0.f; }
    }
}

// ---- prep (identical layouts to R13) ----
__global__ void prep_kernel(const float* __restrict__ fW1, const float* __restrict__ fW2,
                            const float* __restrict__ fW3, const float* __restrict__ Whh,
                            const float* __restrict__ oW1, const float* __restrict__ oW2) {
    for (int i = blockIdx.x * blockDim.x + threadIdx.x; i < 123813;
         i += gridDim.x * blockDim.x) {
        if (i < 28600) {
            int qq = i >> 1, r = i & 1;
            int kp = qq / 275, n = qq % 275;
            int k = 2 * kp + r;
            g_W1P[i] = (k < 101) ? fW1[n * 101 + k] : 0.f;
        } else if (i < 42600) {
            int idx = i - 28600;
            int kp = idx / 100, n = idx % 100;
            int k0 = 2 * kp, k1 = 2 * kp + 1;
            float v0 = (k0 < 275) ? fW3[n * 275 + k0] : 0.f;
            float v1 = (k1 < 275) ? fW3[n * 275 + k1] : 0.f;
            __half2 hv = __floats2half2_rn(v0, v1);
            g_W3H[idx] = *(unsigned int*)&hv;
        } else if (i < 80688) {
            int idx = i - 42600;
            int k = idx / 138, jj = idx % 138;
            int n0 = 2 * jj, n1 = 2 * jj + 1;
            float v0 = (k < 275) ? fW2[n0 * 275 + k] : 0.f;
            float v1 = (k < 275 && n1 < 275) ? fW2[n1 * 275 + k] : 0.f;
            g_W2H[idx] = __floats2half2_rn(v0, v1);
        } else if (i < 110688) {
            int jj = i - 80688, k = jj / 300, n = jj % 300;
            g_WhhT[jj] = Whh[n * 100 + k];
        } else if (i < 118188) {
            int jj = i - 110688, k = jj / 75, n = jj % 75;
            g_oW1T[jj] = oW1[n * 100 + k];
        } else {
            int jj = i - 118188, k = jj / 75, n = jj % 75;
            g_oW2T[jj] = oW2[n * 75 + k];
        }
    }
}

// ---- encode: each half runs one batch row ----
__global__ void __launch_bounds__(NTHR, 1) encode_kernel(
        const float* __restrict__ past, const float* __restrict__ h0,
        const float* __restrict__ fb1, const float* __restrict__ fb2,
        const float* __restrict__ fb3,
        const float* __restrict__ Wih, const float* __restrict__ bih,
        const float* __restrict__ bhh) {
    extern __shared__ float sm[];
    int tid = threadIdx.x;
    int hbf = tid / HALF, ht = tid - hbf * HALF;
    int bid = 1 + hbf;
    float* hb = sm + OFF_HALF + hbf * HB_STRIDE;
    int r = blockIdx.x * 2 + hbf;

    load_shared_weights(tid, sm);

    float rb1 = (ht < NF) ? __ldg(fb1 + ht) : 0.f;
    float rb2a = 0.f, rb2b = 0.f;
    if (ht < 138) {
        rb2a = __ldg(fb2 + 2 * ht);
        rb2b = (2 * ht + 1 < NF) ? __ldg(fb2 + 2 * ht + 1) : 0.f;
    }
    float rb3 = (ht < HH) ? __ldg(fb3 + ht) : 0.f;

    float* s_y = hb + HB_Y;
    float* s_u = hb + HB_L2P;     // [200] scratch
    float* s_inn = hb + HB_L3P;   // [100]
    float* s_hn = hb + HB_A2;     // [100] (rewritten by L2 combine before L3 reads)
    if (ht < HH) s_y[ht] = h0[r * HH + ht];
    __syncthreads();

    float tprev = 0.f;
    for (int step = 0; step < TP; step++) {
        float tcur = past[(r * TP + step) * 2];
        float t0 = (step == 0) ? tcur - 1.f : tprev;
        integrate2(ht, bid, sm, hb, t0, tcur, rb1, rb2a, rb2b, rb3);

        float x = past[(r * TP + step) * 2 + 1];
        const float4* y4 = (const float4*)(hb + HB_Y);
        for (int jj = ht; jj < 300; jj += HALF) {
            float bh = __ldg(bhh + jj);
            float a0 = bh, a1 = 0.f, b0 = 0.f, b1 = 0.f;
#pragma unroll
            for (int k = 0; k < 100; k += 4) {
                float w0 = __ldcg(g_WhhT + k * 300 + jj);
                float w1 = __ldcg(g_WhhT + (k + 1) * 300 + jj);
                float w2 = __ldcg(g_WhhT + (k + 2) * 300 + jj);
                float w3 = __ldcg(g_WhhT + (k + 3) * 300 + jj);
                float4 y = y4[k >> 2];
                a0 = fmaf(w0, y.x, a0); a1 = fmaf(w1, y.y, a1);
                b0 = fmaf(w2, y.z, b0); b1 = fmaf(w3, y.w, b1);
            }
            float a = (a0 + a1) + (b0 + b1);
            float gi = fmaf(__ldg(Wih + jj), x, __ldg(bih + jj));
            if (jj < 200) s_u[jj] = gi + a;
            else { s_inn[jj - 200] = gi; s_hn[jj - 200] = a; }
        }
        hbar(bid);
        if (ht < HH) {
            float rr = sigm1(s_u[ht]);
            float zz = sigm1(s_u[HH + ht]);
            float nn = tanhf(s_inn[ht] + rr * s_hn[ht]);
            s_y[ht] = (1.f - zz) * nn + zz * s_y[ht];
        }
        hbar(bid);
        tprev = tcur;
    }
    if (ht < HH) g_hB[r * HH + ht] = s_y[ht];
}

// ---- decoder head ----
__global__ void gx_kernel(const float* __restrict__ gW1, const float* __restrict__ gb1,
                          const float* __restrict__ gW2, const float* __restrict__ gb2,
                          const float* __restrict__ gW3, const float* __restrict__ gb3) {
    int b = blockIdx.x, tid = threadIdx.x;
    __shared__ float sh[HH], s1[HGG], s2[HGG];
    for (int k = tid; k < HH; k += blockDim.x) sh[k] = g_hB[b * HH + k];
    __syncthreads();
    if (tid < HGG) {
        float a = __ldg(gb1 + tid);
        const float* w = gW1 + tid * HH;
        for (int k = 0; k < HH; k++) a = fmaf(__ldg(w + k), sh[k], a);
        s1[tid] = leaky1(a);
    }
    __syncthreads();
    if (tid < HGG) {
        float a = __ldg(gb2 + tid);
        const float* w = gW2 + tid * HGG;
        for (int k = 0; k < HGG; k++) a = fmaf(__ldg(w + k), s1[k], a);
        s2[tid] = leaky1(a);
    }
    __syncthreads();
    if (tid < 2) {
        float a = __ldg(gb3 + tid);
        const float* w = gW3 + tid * HGG;
        for (int k = 0; k < HGG; k++) a = fmaf(__ldg(w + k), s2[k], a);
        g_gx[b * 2 + tid] = a;
    }
}

__global__ void z0_kernel(const float* __restrict__ eps) {
    int b = blockIdx.x, h = threadIdx.x;
    float loc, scale;
    if (b < NB / 2) {
        loc   = g_gx[(2 * b) * 2 + 0];
        scale = g_gx[(2 * b + 1) * 2 + 0];
    } else {
        int i = 2 * (b - NB / 2);
        loc   = fabsf(g_gx[i * 2 + 1]);
        scale = fabsf(g_gx[(i + 1) * 2 + 1]);
    }
    g_z0[b * HH + h] = loc + scale * eps[h * NB + b];
}

// ---- rollout output MLP (per half, one row) ----
__device__ __forceinline__ void out_mlp(int ht, int bid, float* hb, int r, int s,
        float rob1, float rob2,
        const float* __restrict__ oW3, const float* __restrict__ ob3,
        float* __restrict__ out) {
    float* s_o1 = hb + HB_HID;
    float* s_o2 = hb + HB_A2;
    if (ht < HOO) {
        const float4* y4 = (const float4*)(hb + HB_Y);
        float a0 = rob1, a1 = 0.f, b0 = 0.f, b1 = 0.f;
#pragma unroll
        for (int k = 0; k < 100; k += 4) {
            float w0 = __ldcg(g_oW1T + k * 75 + ht);
            float w1 = __ldcg(g_oW1T + (k + 1) * 75 + ht);
            float w2 = __ldcg(g_oW1T + (k + 2) * 75 + ht);
            float w3 = __ldcg(g_oW1T + (k + 3) * 75 + ht);
            float4 y = y4[k >> 2];
            a0 = fmaf(w0, y.x, a0); a1 = fmaf(w1, y.y, a1);
            b0 = fmaf(w2, y.z, b0); b1 = fmaf(w3, y.w, b1);
        }
        s_o1[ht] = leaky1((a0 + a1) + (b0 + b1));
    }
    hbar(bid);
    if (ht < HOO) {
        float a0 = rob2, a1 = 0.f;
#pragma unroll
        for (int k = 0; k < 74; k += 2) {
            float w0 = __ldcg(g_oW2T + k * 75 + ht);
            float w1 = __ldcg(g_oW2T + (k + 1) * 75 + ht);
            a0 = fmaf(w0, s_o1[k], a0);
            a1 = fmaf(w1, s_o1[k + 1], a1);
        }
        a0 = fmaf(__ldcg(g_oW2T + 74 * 75 + ht), s_o1[74], a0);
        s_o2[ht] = leaky1(a0 + a1);
    }
    hbar(bid);
    if (ht < 32) {
        float a0 = 0.f;
        for (int k = ht; k < HOO; k += 32)
            a0 = fmaf(__ldg(oW3 + k), s_o2[k], a0);
#pragma unroll
        for (int o = 16; o; o >>= 1)
            a0 += __shfl_down_sync(0xffffffffu, a0, o);
        if (ht == 0) out[r * TFUT + s] = a0 + __ldg(ob3);
    }
    hbar(bid);
}

__global__ void __launch_bounds__(NTHR, 1) rollout_kernel(
        const float* __restrict__ tf_,
        const float* __restrict__ fb1, const float* __restrict__ fb2,
        const float* __restrict__ fb3,
        const float* __restrict__ ob1, const float* __restrict__ ob2,
        const float* __restrict__ oW3, const float* __restrict__ ob3,
        float* __restrict__ out) {
    extern __shared__ float sm[];
    int tid = threadIdx.x;
    int hbf = tid / HALF, ht = tid - hbf * HALF;
    int bid = 1 + hbf;
    float* hb = sm + OFF_HALF + hbf * HB_STRIDE;
    int r = blockIdx.x * 2 + hbf;

    load_shared_weights(tid, sm);

    float rb1 = (ht < NF) ? __ldg(fb1 + ht) : 0.f;
    float rb2a = 0.f, rb2b = 0.f;
    if (ht < 138) {
        rb2a = __ldg(fb2 + 2 * ht);
        rb2b = (2 * ht + 1 < NF) ? __ldg(fb2 + 2 * ht + 1) : 0.f;
    }
    float rb3 = (ht < HH) ? __ldg(fb3 + ht) : 0.f;
    float rob1 = (ht < HOO) ? __ldg(ob1 + ht) : 0.f;
    float rob2 = (ht < HOO) ? __ldg(ob2 + ht) : 0.f;

    float* s_y = hb + HB_Y;
    if (ht < HH) s_y[ht] = g_z0[r * HH + ht];
    __syncthreads();

    out_mlp(ht, bid, hb, r, 0, rob1, rob2, oW3, ob3, out);

    float tprev = tf_[r * TFUT];
    for (int s = 1; s < TFUT; s++) {
        float tcur = tf_[r * TFUT + s];
        integrate2(ht, bid, sm, hb, tprev, tcur, rb1, rb2a, rb2b, rb3);
        out_mlp(ht, bid, hb, r, s, rob1, rob2, oW3, ob3, out);
        tprev = tcur;
    }
}

extern "C" void kernel_launch(void* const* d_in, const int* in_sizes, int n_in,
                              void* d_out, int out_size) {
    const float* past = (const float*)d_in[0];
    const float* h0   = (const float*)d_in[1];
    const float* t_fu = (const float*)d_in[2];
    const float* eps  = (const float*)d_in[3];
    const float* fW1  = (const float*)d_in[4];
    const float* fb1  = (const float*)d_in[5];
    const float* fW2  = (const float*)d_in[6];
    const float* fb2  = (const float*)d_in[7];
    const float* fW3  = (const float*)d_in[8];
    const float* fb3  = (const float*)d_in[9];
    const float* Wih  = (const float*)d_in[10];
    const float* Whh  = (const float*)d_in[11];
    const float* bih  = (const float*)d_in[12];
    const float* bhh  = (const float*)d_in[13];
    const float* gW1  = (const float*)d_in[14];
    const float* gb1  = (const float*)d_in[15];
    const float* gW2  = (const float*)d_in[16];
    const float* gb2  = (const float*)d_in[17];
    const float* gW3  = (const float*)d_in[18];
    const float* gb3  = (const float*)d_in[19];
    const float* oW1  = (const float*)d_in[20];
    const float* ob1  = (const float*)d_in[21];
    const float* oW2  = (const float*)d_in[22];
    const float* ob2  = (const float*)d_in[23];
    const float* oW3  = (const float*)d_in[24];
    const float* ob3  = (const float*)d_in[25];
    float* out = (float*)d_out;

    static bool attr_done = false;
    if (!attr_done) {
        cudaFuncSetAttribute(encode_kernel,
                             cudaFuncAttributeMaxDynamicSharedMemorySize, SMEM_BYTES);
        cudaFuncSetAttribute(rollout_kernel,
                             cudaFuncAttributeMaxDynamicSharedMemorySize, SMEM_BYTES);
        attr_done = true;
    }

    prep_kernel<<<192, 256>>>(fW1, fW2, fW3, Whh, oW1, oW2);
    encode_kernel<<<NCTA, NTHR, SMEM_BYTES>>>(past, h0, fb1, fb2, fb3, Wih, bih, bhh);
    gx_kernel<<<NB, 96>>>(gW1, gb1, gW2, gb2, gW3, gb3);
    z0_kernel<<<NB, HH>>>(eps);
    rollout_kernel<<<NCTA, NTHR, SMEM_BYTES>>>(t_fu, fb1, fb2, fb3,
                                               ob1, ob2, oW3, ob3, out);
}